// round 15
// baseline (speedup 1.0000x reference)
#include <cuda_runtime.h>
#include <cuda_fp16.h>
#include <cstdint>

#define B_SIZE 4096
#define T_LEN  2048
#define NSEQ   8
#define NGROUP (B_SIZE / NSEQ)   // 512
#define THREADS 128
#define GRID   128               // 128 CTAs x 4 warps = 512 warps = NGROUP

__device__ int g_order[B_SIZE];

// ---- transcendentals ----
__device__ __forceinline__ float tanha(float x) {
    float r; asm("tanh.approx.f32 %0, %1;" : "=f"(r) : "f"(x)); return r;
}
__device__ __forceinline__ float ex2f(float x) {
    float r; asm("ex2.approx.f32 %0, %1;" : "=f"(r) : "f"(x)); return r;
}
#define L2E 1.4426950408889634f
__device__ __forceinline__ float sigf(float z) { return fmaf(0.5f, tanha(0.5f * z), 0.5f); }

__device__ __forceinline__ __half2 tanh_h2(__half2 v) {
    uint32_t a = *reinterpret_cast<uint32_t*>(&v), r;
    asm("tanh.approx.f16x2 %0, %1;" : "=r"(r) : "r"(a));
    return *reinterpret_cast<__half2*>(&r);
}
__device__ __forceinline__ uint32_t packh2(float lo, float hi) {
    __half2 h = __floats2half2_rn(lo, hi);
    return *reinterpret_cast<uint32_t*>(&h);
}

// D(16x8,f32) += A(16x16,f16,row) x B(16x8,f16,col)
__device__ __forceinline__ void mma16816(float* d, const uint32_t* a, uint32_t b0, uint32_t b1) {
    asm("mma.sync.aligned.m16n8k16.row.col.f32.f16.f16.f32 "
        "{%0,%1,%2,%3}, {%4,%5,%6,%7}, {%8,%9}, {%0,%1,%2,%3};"
        : "+f"(d[0]), "+f"(d[1]), "+f"(d[2]), "+f"(d[3])
        : "r"(a[0]), "r"(a[1]), "r"(a[2]), "r"(a[3]), "r"(b0), "r"(b1));
}

// ---- LPT scheduler: order tasks longest-first (16-step buckets) ----
__global__ void __launch_bounds__(128)
schedule_kernel(const int* __restrict__ lengths)
{
    __shared__ int s_hist[128];
    __shared__ int s_base[128];
    const int tid = threadIdx.x;
    s_hist[tid] = 0;
    __syncthreads();
    for (int i = tid; i < B_SIZE; i += 128) {
        int b = (T_LEN - lengths[i]) >> 4;
        atomicAdd(&s_hist[b], 1);
    }
    __syncthreads();
    if (tid == 0) {
        int acc = 0;
        for (int b = 0; b < 128; b++) { s_base[b] = acc; acc += s_hist[b]; }
    }
    __syncthreads();
    s_hist[tid] = 0;
    __syncthreads();
    for (int i = tid; i < B_SIZE; i += 128) {
        int b = (T_LEN - lengths[i]) >> 4;
        int pos = s_base[b] + atomicAdd(&s_hist[b], 1);
        g_order[pos] = i;
    }
}

__global__ void __launch_bounds__(THREADS)
bilstm_kernel(const float* __restrict__ x,
              const int*   __restrict__ lengths,
              const float* __restrict__ w_ih,
              const float* __restrict__ w_hh,
              const float* __restrict__ b_ih,
              const float* __restrict__ b_hh,
              const float* __restrict__ fc_w,
              const float* __restrict__ fc_b,
              const float* __restrict__ fc2_w,
              const float* __restrict__ fc2_b,
              float* __restrict__ out)
{
    // per-warp h buffer: 8 seqs x 32 units, f16, layout [seq][unit]
    __shared__ __align__(16) __half s_h[4 * NSEQ * 32];

    const int tid  = threadIdx.x;
    const int lane = tid & 31;
    const int wid  = tid >> 5;
    const int g0   = lane >> 2;    // 0..7  (fragment "group")
    const int tg   = lane & 3;     // 0..3  (thread-in-group)

    __half* hbuf = s_h + wid * (NSEQ * 32);
    const int group = blockIdx.x * 4 + wid;          // 0..511, one group per warp

    // ---- W as mma A-fragments (64 regs). i/f/o rows pre-scaled by 0.5 ----
    // tiles t: rows 16t+g0, 16t+8+g0. tiles 0-1: i, 2-3: f, 4-5: g, 6-7: o
    uint32_t A[8][2][4];
    #pragma unroll
    for (int t = 0; t < 8; t++) {
        const int r0 = 16 * t + g0;
        const int r1 = r0 + 8;
        const float sc = (t == 4 || t == 5) ? 1.0f : 0.5f;
        #pragma unroll
        for (int kt = 0; kt < 2; kt++) {
            const int cb = 16 * kt + 2 * tg;
            A[t][kt][0] = packh2(w_hh[r0 * 32 + cb]     * sc, w_hh[r0 * 32 + cb + 1] * sc);
            A[t][kt][1] = packh2(w_hh[r1 * 32 + cb]     * sc, w_hh[r1 * 32 + cb + 1] * sc);
            A[t][kt][2] = packh2(w_hh[r0 * 32 + cb + 8] * sc, w_hh[r0 * 32 + cb + 9] * sc);
            A[t][kt][3] = packh2(w_hh[r1 * 32 + cb + 8] * sc, w_hh[r1 * 32 + cb + 9] * sc);
        }
    }
    // bias + w_ih for this lane's 16 D-rows (row = g0 + 8m), same prescale
    float bs[16], wx[16];
    #pragma unroll
    for (int m = 0; m < 16; m++) {
        const int row = g0 + 8 * m;
        const float sc = (m >= 8 && m < 12) ? 1.0f : 0.5f;   // m 8..11 = g rows 64..95
        bs[m] = (b_ih[row] + b_hh[row]) * sc;
        wx[m] = w_ih[row] * sc;
    }

    // ---- this lane's two D-column sequences ----
    const int sA = 2 * tg, sB = sA + 1;
    const int taskA = g_order[group * NSEQ + sA];
    const int taskB = g_order[group * NSEQ + sB];
    const int lenA = lengths[taskA];
    const int lenB = lengths[taskB];
    const float* xbA = x + (size_t)taskA * T_LEN;
    const float* xbB = x + (size_t)taskB * T_LEN;
    const int tmax = __reduce_max_sync(0xffffffffu, lenA > lenB ? lenA : lenB);

    // zero h buffer (32 x uint4 = 512 B), init c
    ((uint4*)hbuf)[lane] = make_uint4(0u, 0u, 0u, 0u);
    float c[4][2] = {};
    __syncwarp();

    const __half2 h05 = __float2half2_rn(0.5f);

    float xvA = __ldg(xbA + (lenA - 1));
    float xvB = __ldg(xbB + (lenB - 1));

    for (int k = 0; k < tmax; k++) {
        // prefetch next x (clamped)
        int tnA = lenA - 2 - k; if (tnA < 0) tnA = 0;
        int tnB = lenB - 2 - k; if (tnB < 0) tnB = 0;
        const float xnA = __ldg(xbA + tnA);
        const float xnB = __ldg(xbB + tnB);
        const bool vA = (k < lenA);
        const bool vB = (k < lenB);

        // B fragments: seq g0, unit pairs {2tg,2tg+1}, +8, +16, +24
        const uint32_t* hrow = reinterpret_cast<const uint32_t*>(hbuf + g0 * 32);
        const uint32_t b00 = hrow[tg];
        const uint32_t b01 = hrow[tg + 4];
        const uint32_t b10 = hrow[tg + 8];
        const uint32_t b11 = hrow[tg + 12];
        __syncwarp();   // all reads done before any store below

        // D init (bias + w_ih*x, prescaled) then 16 mma on tensor pipe
        float D[8][4];
        #pragma unroll
        for (int t = 0; t < 8; t++) {
            D[t][0] = fmaf(wx[2 * t],     xvA, bs[2 * t]);
            D[t][1] = fmaf(wx[2 * t],     xvB, bs[2 * t]);
            D[t][2] = fmaf(wx[2 * t + 1], xvA, bs[2 * t + 1]);
            D[t][3] = fmaf(wx[2 * t + 1], xvB, bs[2 * t + 1]);
            mma16816(D[t], A[t][0], b00, b01);
            mma16816(D[t], A[t][1], b10, b11);
        }

        // activations: 4 (unit, seq-pair) states per lane
        #pragma unroll
        for (int j = 0; j < 4; j++) {
            const int ti = j >> 1;
            const int lo = (j & 1) * 2;
            const __half2 ih = __hfma2(tanh_h2(__floats2half2_rn(D[ti][lo],     D[ti][lo + 1])),     h05, h05);
            const __half2 fh = __hfma2(tanh_h2(__floats2half2_rn(D[2 + ti][lo], D[2 + ti][lo + 1])), h05, h05);
            const __half2 gh =         tanh_h2(__floats2half2_rn(D[4 + ti][lo], D[4 + ti][lo + 1]));
            const __half2 oh = __hfma2(tanh_h2(__floats2half2_rn(D[6 + ti][lo], D[6 + ti][lo + 1])), h05, h05);
            const float2 pv = __half22float2(__hmul2(ih, gh));
            const float2 fv = __half22float2(fh);
            c[j][0] = fmaf(fv.x, c[j][0], pv.x);
            c[j][1] = fmaf(fv.y, c[j][1], pv.y);
            const __half2 hh = __hmul2(oh, tanh_h2(__floats2half2_rn(c[j][0], c[j][1])));
            const int u = g0 + ((j & 1) << 3) + ((j >> 1) << 4);
            if (vA) hbuf[sA * 32 + u] = __low2half(hh);    // skip store = freeze h
            if (vB) hbuf[sB * 32 + u] = __high2half(hh);
        }
        __syncwarp();
        xvA = xnA; xvB = xnB;
    }

    // ---- FC heads for the 8 sequences (cold path) ----
    #pragma unroll 1
    for (int s = 0; s < NSEQ; s++) {
        const int task = g_order[group * NSEQ + s];
        float u0 = __ldg(fc_b + lane);
        float u1 = __ldg(fc_b + 32 + lane);
        #pragma unroll
        for (int kk = 0; kk < 32; kk++) {
            const float hk = __half2float(hbuf[s * 32 + kk]);
            u0 = fmaf(__ldg(fc_w + lane * 32 + kk),        hk, u0);
            u1 = fmaf(__ldg(fc_w + (32 + lane) * 32 + kk), hk, u1);
        }
        u0 = (u0 > 0.f) ? u0 : (ex2f(L2E * u0) - 1.f);
        u1 = (u1 > 0.f) ? u1 : (ex2f(L2E * u1) - 1.f);
        float part = u0 * __ldg(fc2_w + lane) + u1 * __ldg(fc2_w + 32 + lane);
        #pragma unroll
        for (int sh = 16; sh; sh >>= 1) part += __shfl_xor_sync(0xffffffffu, part, sh);
        if (lane == 0) out[task] = sigf(part + __ldg(fc2_b));
    }
}

extern "C" void kernel_launch(void* const* d_in, const int* in_sizes, int n_in,
                              void* d_out, int out_size)
{
    const float* x       = (const float*)d_in[0];
    const int*   lengths = (const int*)  d_in[1];
    const float* w_ih    = (const float*)d_in[2];
    const float* w_hh    = (const float*)d_in[3];
    const float* b_ih    = (const float*)d_in[4];
    const float* b_hh    = (const float*)d_in[5];
    const float* fc_w    = (const float*)d_in[6];
    const float* fc_b    = (const float*)d_in[7];
    const float* fc2_w   = (const float*)d_in[8];
    const float* fc2_b   = (const float*)d_in[9];
    float* out = (float*)d_out;

    schedule_kernel<<<1, 128>>>(lengths);
    bilstm_kernel<<<GRID, THREADS>>>(x, lengths, w_ih, w_hh, b_ih, b_hh,
                                     fc_w, fc_b, fc2_w, fc2_b, out);
}